// round 7
// baseline (speedup 1.0000x reference)
#include <cuda_runtime.h>
#include <math.h>

#define Bv 64
#define Tv 1024
#define Hv 512
#define NCTA 128

// ---------------- device scratch ----------------
__device__ float g_Xr[(size_t)Tv * Bv * Hv];   // pre-projected r inputs [m][j], m=t*64+b
__device__ float g_Xz[(size_t)Tv * Bv * Hv];
__device__ float g_Xh[(size_t)Tv * Bv * Hv];
__device__ float g_HS[(size_t)Tv * Bv * Hv];   // layer-0 hidden outputs
__device__ float g_pA[8  * Bv * 1024];         // split-K partials: rz GEMM
__device__ float g_pB[16 * Bv * Hv];           // split-K partials: h~ GEMM
__device__ float g_h [Bv * Hv];                // current hidden state
__device__ unsigned int g_bar;                 // grid barrier counter

__global__ void reset_bar() { g_bar = 0u; }

__device__ __forceinline__ void gbar(unsigned int &target) {
    __syncthreads();
    if (threadIdx.x == 0) {
        __threadfence();
        atomicAdd(&g_bar, 1u);
        target += NCTA;
        while (*(volatile unsigned int *)&g_bar < target) { }
        __threadfence();
    }
    __syncthreads();
}

// ---------------- pre-projection GEMM ----------------
// For all m in [0,65536), j in [0,1536):
//   j<512  : g_Xr[m][j]      = sum_k A[m][k]*Wr[j][k]      + br[j]
//   j<1024 : g_Xz[m][j-512]  = sum_k A[m][k]*Wz[j-512][k]  + bz[..]
//   else   : g_Xh[m][j-1024] = sum_k A[m][k]*Wh[j-1024][k] + bh[..]
// GATHER=1: A[m] = emb[tokens[b*T+t]] (t=m>>6, b=m&63);  GATHER=0: A = g_HS.
template <int GATHER>
__global__ void __launch_bounds__(256) xproj_kernel(
    const float *__restrict__ emb, const int *__restrict__ tokens,
    const float *__restrict__ Wr, const float *__restrict__ Wz,
    const float *__restrict__ Wh,
    const float *__restrict__ br, const float *__restrict__ bz,
    const float *__restrict__ bh,
    int K, int ldW)
{
    __shared__ __align__(16) float As[16][68];
    __shared__ __align__(16) float Bs[16][68];
    __shared__ const float *rowp[64];
    __shared__ const float *colp[64];

    const int tid = threadIdx.x;
    const int m0 = blockIdx.x * 64;
    const int j0 = blockIdx.y * 64;

    if (tid < 64) {
        int m = m0 + tid;
        if (GATHER) {
            int b = m & 63, t = m >> 6;
            rowp[tid] = emb + (size_t)tokens[b * Tv + t] * 256;
        } else {
            rowp[tid] = g_HS + (size_t)m * Hv;
        }
    } else if (tid < 128) {
        int j = j0 + tid - 64;
        const float *w;
        if (j < 512)       w = Wr + (size_t)j * ldW;
        else if (j < 1024) w = Wz + (size_t)(j - 512) * ldW;
        else               w = Wh + (size_t)(j - 1024) * ldW;
        colp[tid - 64] = w;
    }
    __syncthreads();

    const int tx = tid & 15, ty = tid >> 4;
    float acc[4][4];
#pragma unroll
    for (int i = 0; i < 4; i++)
#pragma unroll
        for (int j = 0; j < 4; j++) acc[i][j] = 0.0f;

    const int r = tid >> 2, kq = tid & 3;
    for (int k0 = 0; k0 < K; k0 += 16) {
        float4 va = *(const float4 *)(rowp[r] + k0 + kq * 4);
        As[kq * 4 + 0][r] = va.x; As[kq * 4 + 1][r] = va.y;
        As[kq * 4 + 2][r] = va.z; As[kq * 4 + 3][r] = va.w;
        float4 vb = *(const float4 *)(colp[r] + k0 + kq * 4);
        Bs[kq * 4 + 0][r] = vb.x; Bs[kq * 4 + 1][r] = vb.y;
        Bs[kq * 4 + 2][r] = vb.z; Bs[kq * 4 + 3][r] = vb.w;
        __syncthreads();
#pragma unroll
        for (int k = 0; k < 16; k++) {
            float a[4], w[4];
            *(float4 *)a = *(const float4 *)&As[k][ty * 4];
            *(float4 *)w = *(const float4 *)&Bs[k][tx * 4];
#pragma unroll
            for (int i = 0; i < 4; i++)
#pragma unroll
                for (int j = 0; j < 4; j++)
                    acc[i][j] = fmaf(a[i], w[j], acc[i][j]);
        }
        __syncthreads();
    }

    float *dst; const float *bias; int jloc;
    if (j0 < 512)       { dst = g_Xr; bias = br; jloc = j0; }
    else if (j0 < 1024) { dst = g_Xz; bias = bz; jloc = j0 - 512; }
    else                { dst = g_Xh; bias = bh; jloc = j0 - 1024; }
    const int c0 = jloc + tx * 4;
    const float b0 = bias[c0], b1 = bias[c0 + 1], b2 = bias[c0 + 2], b3 = bias[c0 + 3];
#pragma unroll
    for (int i = 0; i < 4; i++) {
        int m = m0 + ty * 4 + i;
        float4 v = make_float4(acc[i][0] + b0, acc[i][1] + b1,
                               acc[i][2] + b2, acc[i][3] + b3);
        *(float4 *)&dst[(size_t)m * Hv + c0] = v;
    }
}

// ---------------- persistent GRU recurrence ----------------
// 128 CTAs x 256 threads, all co-resident. 3 grid barriers per time step.
// Phase A: pA[kb][b][col1024] partial of h @ [Wr_h;Wz_h]^T  (kb: 8 k-blocks of 64)
// Phase B: rh = sigmoid(xr + sum pA) * h  staged per k-chunk, then
//          pB[kb2][b][col512] partial of rh @ Wh_h^T        (kb2: 16 k-blocks of 32)
// Phase C: z = sigmoid(xz + sum pA[.,512+j]); h' = h + z*(tanh(xh + sum pB) - h)
__global__ void __launch_bounds__(256) gru_rec_kernel(
    const float *__restrict__ Wr, const float *__restrict__ Wz,
    const float *__restrict__ Wh,
    int D, int ldW, int store_hs)
{
    __shared__ __align__(16) float Wa[64 * 68];
    __shared__ __align__(16) float Wb[32 * 68];
    __shared__ __align__(16) float Sa[64 * 68];

    const int tid = threadIdx.x;
    const int cid = blockIdx.x;
    const int tx = tid & 15, ty = tid >> 4;
    const int nb = cid & 15, kb = cid >> 4;     // phase A role
    const int nb2 = cid & 7, kb2 = cid >> 3;    // phase B role

    // Preload recurrent weight slices once (h-part = columns [D, D+512)).
    for (int e = tid; e < 64 * 64; e += 256) {
        int k = e & 63, j = e >> 6;
        int jg = nb * 64 + j;
        const float *w = (jg < 512) ? (Wr + (size_t)jg * ldW)
                                    : (Wz + (size_t)(jg - 512) * ldW);
        Wa[k * 68 + j] = w[D + kb * 64 + k];
    }
    for (int e = tid; e < 32 * 64; e += 256) {
        int k = e & 31, j = e >> 5;
        Wb[k * 68 + j] = Wh[(size_t)(nb2 * 64 + j) * ldW + D + kb2 * 32 + k];
    }
    __stcg(&g_h[cid * 256 + tid], 0.0f);   // h0 = 0

    unsigned int target = 0;
    gbar(target);

    for (int t = 0; t < Tv; t++) {
        const size_t xb = (size_t)t * Bv * Hv;

        // ---- Phase A: stage h[:, kb*64..+64) into Sa[k][b], then 64x64x64 GEMM
        for (int e = tid; e < 64 * 16; e += 256) {
            int kq = e & 15, b = e >> 4;
            float4 v = __ldcg((const float4 *)&g_h[b * Hv + kb * 64 + kq * 4]);
            Sa[(kq * 4 + 0) * 68 + b] = v.x; Sa[(kq * 4 + 1) * 68 + b] = v.y;
            Sa[(kq * 4 + 2) * 68 + b] = v.z; Sa[(kq * 4 + 3) * 68 + b] = v.w;
        }
        __syncthreads();
        {
            float acc[4][4];
#pragma unroll
            for (int i = 0; i < 4; i++)
#pragma unroll
                for (int j = 0; j < 4; j++) acc[i][j] = 0.0f;
#pragma unroll 8
            for (int k = 0; k < 64; k++) {
                float a[4], w[4];
                *(float4 *)a = *(const float4 *)&Sa[k * 68 + ty * 4];
                *(float4 *)w = *(const float4 *)&Wa[k * 68 + tx * 4];
#pragma unroll
                for (int i = 0; i < 4; i++)
#pragma unroll
                    for (int j = 0; j < 4; j++)
                        acc[i][j] = fmaf(a[i], w[j], acc[i][j]);
            }
#pragma unroll
            for (int i = 0; i < 4; i++) {
                int b = ty * 4 + i;
                float4 v = make_float4(acc[i][0], acc[i][1], acc[i][2], acc[i][3]);
                __stcg((float4 *)&g_pA[((size_t)kb * 64 + b) * 1024 + nb * 64 + tx * 4], v);
            }
        }
        gbar(target);

        // ---- Phase B: stage rh[k][b] for k-chunk kb2, then 64x64x32 GEMM
        for (int e = tid; e < 32 * 64; e += 256) {
            int k = e & 31, b = e >> 5;
            int kg = kb2 * 32 + k;
            float s = g_Xr[xb + (size_t)b * Hv + kg];
#pragma unroll
            for (int p = 0; p < 8; p++)
                s += __ldcg(&g_pA[((size_t)p * 64 + b) * 1024 + kg]);
            float rg = 1.0f / (1.0f + expf(-s));
            Sa[k * 68 + b] = rg * __ldcg(&g_h[b * Hv + kg]);
        }
        __syncthreads();
        {
            float acc[4][4];
#pragma unroll
            for (int i = 0; i < 4; i++)
#pragma unroll
                for (int j = 0; j < 4; j++) acc[i][j] = 0.0f;
#pragma unroll 8
            for (int k = 0; k < 32; k++) {
                float a[4], w[4];
                *(float4 *)a = *(const float4 *)&Sa[k * 68 + ty * 4];
                *(float4 *)w = *(const float4 *)&Wb[k * 68 + tx * 4];
#pragma unroll
                for (int i = 0; i < 4; i++)
#pragma unroll
                    for (int j = 0; j < 4; j++)
                        acc[i][j] = fmaf(a[i], w[j], acc[i][j]);
            }
#pragma unroll
            for (int i = 0; i < 4; i++) {
                int b = ty * 4 + i;
                float4 v = make_float4(acc[i][0], acc[i][1], acc[i][2], acc[i][3]);
                __stcg((float4 *)&g_pB[((size_t)kb2 * 64 + b) * Hv + nb2 * 64 + tx * 4], v);
            }
        }
        gbar(target);

        // ---- Phase C: h update (1 element per thread)
        {
            int e = cid * 256 + tid;          // [0, 32768)
            int b = e >> 9, j = e & 511;
            float sz = g_Xz[xb + (size_t)b * Hv + j];
#pragma unroll
            for (int p = 0; p < 8; p++)
                sz += __ldcg(&g_pA[((size_t)p * 64 + b) * 1024 + 512 + j]);
            float sh = g_Xh[xb + (size_t)b * Hv + j];
#pragma unroll
            for (int p = 0; p < 16; p++)
                sh += __ldcg(&g_pB[((size_t)p * 64 + b) * Hv + j]);
            float h = __ldcg(&g_h[b * Hv + j]);
            float z = 1.0f / (1.0f + expf(-sz));
            float hn = h + z * (tanhf(sh) - h);
            __stcg(&g_h[b * Hv + j], hn);
            if (store_hs)
                g_HS[(size_t)(t * Bv + b) * Hv + j] = hn;
        }
        gbar(target);
    }
}

// ---------------- final FC: out[b][c] = h_last[b] . fcW[c] + fcb[c] ----------------
__global__ void fc_kernel(const float *__restrict__ fcW,
                          const float *__restrict__ fcb,
                          float *__restrict__ out)
{
    int b = threadIdx.x >> 1, c = threadIdx.x & 1;
    float s = 0.0f;
    for (int j = 0; j < Hv; j += 4) {
        float4 hv = *(const float4 *)&g_h[b * Hv + j];
        float4 wv = *(const float4 *)&fcW[c * Hv + j];
        s = fmaf(hv.x, wv.x, s); s = fmaf(hv.y, wv.y, s);
        s = fmaf(hv.z, wv.z, s); s = fmaf(hv.w, wv.w, s);
    }
    out[b * 2 + c] = s + fcb[c];
}

// ---------------- launch ----------------
extern "C" void kernel_launch(void* const* d_in, const int* in_sizes, int n_in,
                              void* d_out, int out_size) {
    const int   *tokens = (const int *)d_in[0];
    const float *emb = (const float *)d_in[1];
    const float *Wr0 = (const float *)d_in[2];
    const float *br0 = (const float *)d_in[3];
    const float *Wz0 = (const float *)d_in[4];
    const float *bz0 = (const float *)d_in[5];
    const float *Wh0 = (const float *)d_in[6];
    const float *bh0 = (const float *)d_in[7];
    const float *Wr1 = (const float *)d_in[8];
    const float *br1 = (const float *)d_in[9];
    const float *Wz1 = (const float *)d_in[10];
    const float *bz1 = (const float *)d_in[11];
    const float *Wh1 = (const float *)d_in[12];
    const float *bh1 = (const float *)d_in[13];
    const float *fcW = (const float *)d_in[14];
    const float *fcb = (const float *)d_in[15];
    float *out = (float *)d_out;

    dim3 gx(1024, 24);

    // Layer 0
    xproj_kernel<1><<<gx, 256>>>(emb, tokens, Wr0, Wz0, Wh0, br0, bz0, bh0,
                                 256, 768);
    reset_bar<<<1, 1>>>();
    gru_rec_kernel<<<NCTA, 256>>>(Wr0, Wz0, Wh0, 256, 768, 1);

    // Layer 1
    xproj_kernel<0><<<gx, 256>>>(nullptr, nullptr, Wr1, Wz1, Wh1, br1, bz1, bh1,
                                 512, 1024);
    reset_bar<<<1, 1>>>();
    gru_rec_kernel<<<NCTA, 256>>>(Wr1, Wz1, Wh1, 512, 1024, 0);

    // Classifier
    fc_kernel<<<1, 128>>>(fcW, fcb, out);
}